// round 6
// baseline (speedup 1.0000x reference)
#include <cuda_runtime.h>

typedef unsigned long long ull;

#define Bb     1024
#define ITEMS  55
#define NSTR   (Bb*ITEMS)    /* 56320 */
#define EOS_TOK 129

#define OFF_CLSEMB 24576          /* 1024*24 */
#define OFF_STREMB 925696         /* 24576 + 1024*55*16 */

#define S1 (-1.4426950408889634f)   /* -log2(e)   : r,z gates */
#define S2 (-2.8853900817779268f)   /* -2*log2(e) : n gate    */

/* ---- scratch (device globals) ---- */
__device__ ull   g_tr[2*128*8];       /* S1*(gi_r+bih_r+bhh_r), unit pairs */
__device__ ull   g_tz[2*128*8];       /* S1*(gi_z+bih_z+bhh_z) */
__device__ ull   g_tn[2*128*8];       /* S2*(gi_n+bih_n) */
__device__ float g_ctab[19*16];
__device__ float g_hbuf[2*NSTR*16];
__device__ float g_hcls[Bb*16];
__device__ unsigned char g_len[NSTR];

__constant__ int c_map[19] = {128,93,41,91,61,34,40,37,33,63,43,47,36,42,96,48,95,46,128};

__device__ __forceinline__ float ex2f(float x) {
    float r; asm("ex2.approx.f32 %0, %1;" : "=f"(r) : "f"(x)); return r;
}
__device__ __forceinline__ float rcpf(float x) {
    float r; asm("rcp.approx.f32 %0, %1;" : "=f"(r) : "f"(x)); return r;
}
__device__ __forceinline__ float ftanh_(float x) {
    /* tanh(x) = 2/(1+e^{-2x}) - 1 ; e^{-2x} = ex2(S2*x) */
    float e = ex2f(S2 * x);
    return fmaf(rcpf(1.f + e), 2.f, -1.f);
}
__device__ __forceinline__ ull pack2(float x, float y) {
    ull r; asm("mov.b64 %0, {%1, %2};" : "=l"(r) : "f"(x), "f"(y)); return r;
}
__device__ __forceinline__ void unpack2(ull v, float& x, float& y) {
    asm("mov.b64 {%0, %1}, %2;" : "=f"(x), "=f"(y) : "l"(v));
}
__device__ __forceinline__ ull ffma2(ull a, ull b, ull c) {
    ull d; asm("fma.rn.f32x2 %0, %1, %2, %3;" : "=l"(d) : "l"(a), "l"(b), "l"(c)); return d;
}
__device__ __forceinline__ ull fadd2(ull a, ull b) {
    ull d; asm("add.rn.f32x2 %0, %1, %2;" : "=l"(d) : "l"(a), "l"(b)); return d;
}

/* ================= K0: precompute scaled gi tables ================= */
__global__ void k_tables(const float* __restrict__ emb,
                         const float* __restrict__ Wf, const float* __restrict__ bif, const float* __restrict__ bhf,
                         const float* __restrict__ Wb, const float* __restrict__ bib, const float* __restrict__ bhb,
                         const float* __restrict__ rW, const float* __restrict__ rb)
{
    int idx = blockIdx.x * blockDim.x + threadIdx.x;
    if (idx < 4096) {
        int dir = idx >> 11;
        int c   = (idx >> 4) & 127;
        int jj  = idx & 15;
        const float* W  = dir ? Wb : Wf;
        const float* bi = dir ? bib : bif;
        const float* bh = dir ? bhb : bhf;
        float e[16];
        #pragma unroll
        for (int d = 0; d < 16; d++) e[d] = (c == 0) ? 0.f : emb[c*16 + d];
        float v[3];
        #pragma unroll
        for (int g = 0; g < 3; g++) {
            float a = bi[g*16 + jj];
            #pragma unroll
            for (int d = 0; d < 16; d++) a += e[d] * W[(g*16 + jj)*16 + d];
            v[g] = a;
        }
        v[0] = S1 * (v[0] + bh[jj]);
        v[1] = S1 * (v[1] + bh[16 + jj]);
        v[2] = S2 * v[2];
        int o = ((dir*128 + c)*8 + (jj >> 1))*2 + (jj & 1);
        ((float*)g_tr)[o] = v[0];
        ((float*)g_tz)[o] = v[1];
        ((float*)g_tn)[o] = v[2];
    } else if (idx < 4096 + 304) {
        int t = idx - 4096;
        int cls = t >> 4, jj = t & 15;
        int c = c_map[cls];
        float v = rb[jj];
        #pragma unroll
        for (int d = 0; d < 16; d++) v += emb[c*16 + d] * rW[jj*16 + d];
        g_ctab[t] = v;
    }
}

/* ================= K1: bidirectional GRU + fused str_emb/len/clsemb ====== */
__global__ void __launch_bounds__(128, 3) k_gru(const int* __restrict__ strs,
                                                const float* __restrict__ Whf, const float* __restrict__ bhf,
                                                const float* __restrict__ Whb, const float* __restrict__ bhb,
                                                const float* __restrict__ emb,
                                                const int* __restrict__ ocl,
                                                float* __restrict__ out_stremb,
                                                float* __restrict__ out_clsemb)
{
    __shared__ ull s_tr[1024], s_tz[1024], s_tn[1024];  /* 24 KB */
    __shared__ float4 semb[520];
    __shared__ unsigned char sch[16*80];
    __shared__ int slen[16];
    int tid = threadIdx.x;
    int dir = blockIdx.y;
    int base = blockIdx.x * 16;

    {
        const float4* s0 = (const float4*)(g_tr + dir*1024);
        const float4* s1 = (const float4*)(g_tz + dir*1024);
        const float4* s2 = (const float4*)(g_tn + dir*1024);
        for (int i = tid; i < 512; i += 128) {
            ((float4*)s_tr)[i] = s0[i];
            ((float4*)s_tz)[i] = s1[i];
            ((float4*)s_tn)[i] = s2[i];
        }
    }
    if (dir == 0) {
        const float4* e4 = (const float4*)emb;
        for (int i = tid; i < 520; i += 128) {
            float4 v = e4[i];
            if (i < 4) v = make_float4(0.f, 0.f, 0.f, 0.f);
            semb[i] = v;
        }
    } else {
        /* fused inv_class_emb: 16 items x 4 float4 */
        if (tid < 64) {
            int it = base + (tid >> 2), d4 = tid & 3;
            int c = c_map[ocl[it]];
            ((float4*)out_clsemb)[it*4 + d4] = ((const float4*)emb)[c*4 + d4];
        }
    }
    const int* sp = strs + (size_t)base * 80;
    for (int i = tid; i < 1280; i += 128) sch[i] = (unsigned char)sp[i];
    __syncthreads();

    int j = tid & 7;
    int s = tid >> 3;
    unsigned gm = 0xFFu << (tid & 24);

    {   /* lengths */
        const unsigned char* ch = &sch[s*80];
        int cnt = 0;
        #pragma unroll
        for (int i = 0; i < 10; i++) cnt += (ch[j*10 + i] != 0);
        #pragma unroll
        for (int o = 4; o; o >>= 1) cnt += __shfl_xor_sync(gm, cnt, o, 8);
        if (j == 0) {
            slen[s] = cnt;
            if (dir == 0) g_len[base + s] = (unsigned char)cnt;
        }
    }
    __syncthreads();

    if (dir == 0) {   /* str_emb */
        float4* o4 = (float4*)out_stremb + (size_t)base * 320;
        for (int it = 0; it < 40; it++) {
            int i = it*128 + tid;
            int ss = i / 320;
            int w = i - ss*320;
            int t = w >> 2, d4 = w & 3;
            int c = (t == slen[ss]) ? EOS_TOK : (int)sch[ss*80 + t];
            o4[i] = semb[c*4 + d4];
        }
    }

    /* pre-scaled weights: unit u0=2j gets wX0[], unit u1=2j+1 gets wX1[]; k-pairs */
    const float* Wp = dir ? Whb : Whf;
    const float* bh = dir ? bhb : bhf;
    int u0 = j * 2, u1 = u0 + 1;
    ull wr0[8], wr1[8], wz0[8], wz1[8], wn0[8], wn1[8];
    #pragma unroll
    for (int m = 0; m < 8; m++) {
        wr0[m] = pack2(S1*Wp[u0*16 + 2*m],      S1*Wp[u0*16 + 2*m+1]);
        wr1[m] = pack2(S1*Wp[u1*16 + 2*m],      S1*Wp[u1*16 + 2*m+1]);
        wz0[m] = pack2(S1*Wp[(16+u0)*16 + 2*m], S1*Wp[(16+u0)*16 + 2*m+1]);
        wz1[m] = pack2(S1*Wp[(16+u1)*16 + 2*m], S1*Wp[(16+u1)*16 + 2*m+1]);
        wn0[m] = pack2(S2*Wp[(32+u0)*16 + 2*m], S2*Wp[(32+u0)*16 + 2*m+1]);
        wn1[m] = pack2(S2*Wp[(32+u1)*16 + 2*m], S2*Wp[(32+u1)*16 + 2*m+1]);
    }
    ull bhn2 = pack2(S2*bh[32 + u0], S2*bh[32 + u1]);   /* (u0, u1) layout */
    const ull NEG1x2 = pack2(-1.f, -1.f);

    int len = slen[s];
    const unsigned char* ch = &sch[s*80];
    ull h2 = 0;
    if (len > 0) {
        int dstep = dir ? -1 : 1;
        int pos = dir ? (len - 1) : 0;
        int c = ch[pos];
        ull gr = s_tr[c*8 + j], gz = s_tz[c*8 + j], gn = s_tn[c*8 + j];
        for (int t = 0; t < len; t++) {
            int pn = pos + dstep;
            int pcl = (t + 1 < len) ? pn : 0;
            int cn = ch[pcl];
            ull grn = s_tr[cn*8 + j], gzn = s_tz[cn*8 + j], gnn = s_tn[cn*8 + j];

            /* aX0 components are (even-k, odd-k) partial sums of unit u0 —
               biases must be added AFTER the cross-pack, in (u0,u1) layout */
            ull aR0 = 0, aR1 = 0, aZ0 = 0, aZ1 = 0, aN0 = 0, aN1 = 0;
            #pragma unroll
            for (int m = 0; m < 8; m++) {
                ull hp = __shfl_sync(gm, h2, m, 8);
                aR0 = ffma2(wr0[m], hp, aR0);
                aR1 = ffma2(wr1[m], hp, aR1);
                aZ0 = ffma2(wz0[m], hp, aZ0);
                aZ1 = ffma2(wz1[m], hp, aZ1);
                aN0 = ffma2(wn0[m], hp, aN0);
                aN1 = ffma2(wn1[m], hp, aN1);
            }
            float x0, x1, y0, y1;
            /* r gate */
            unpack2(aR0, x0, x1); unpack2(aR1, y0, y1);
            ull pr = fadd2(fadd2(pack2(x0, y0), pack2(x1, y1)), gr);
            float p0, p1; unpack2(pr, p0, p1);
            float r0 = rcpf(1.f + ex2f(p0));     /* sigmoid */
            float r1 = rcpf(1.f + ex2f(p1));
            /* z gate */
            unpack2(aZ0, x0, x1); unpack2(aZ1, y0, y1);
            ull pz = fadd2(fadd2(pack2(x0, y0), pack2(x1, y1)), gz);
            unpack2(pz, p0, p1);
            float z0 = rcpf(1.f + ex2f(p0));
            float z1 = rcpf(1.f + ex2f(p1));
            /* n gate: hn = S2*(Wn·h + bhh_n), cross-packed then +bhn2 */
            unpack2(aN0, x0, x1); unpack2(aN1, y0, y1);
            ull hn = fadd2(fadd2(pack2(x0, y0), pack2(x1, y1)), bhn2);
            float hn0, hn1; unpack2(hn, hn0, hn1);
            float gn0, gn1; unpack2(gn, gn0, gn1);
            float e0 = ex2f(fmaf(r0, hn0, gn0));
            float e1 = ex2f(fmaf(r1, hn1, gn1));
            float n0 = fmaf(rcpf(1.f + e0), 2.f, -1.f);
            float n1 = fmaf(rcpf(1.f + e1), 2.f, -1.f);
            /* packed update: h = n + z*(h - n) */
            ull n2 = pack2(n0, n1);
            ull z2 = pack2(z0, z1);
            ull df = ffma2(n2, NEG1x2, h2);
            h2 = ffma2(z2, df, n2);

            gr = grn; gz = gzn; gn = gnn; pos = pn;
        }
    }
    ((ull*)g_hbuf)[((size_t)dir*NSTR + base + s)*8 + j] = h2;
}

/* ================= K2: class-branch vanilla RNN ================= */
__global__ void __launch_bounds__(128) k_cls(const int* __restrict__ ocl,
                                             const float* __restrict__ Whh,
                                             const float* __restrict__ bhh)
{
    __shared__ float sct[19*16];
    __shared__ unsigned char soc[8*55];
    int tid = threadIdx.x;
    int base = blockIdx.x * 8;
    for (int i = tid; i < 304; i += 128) sct[i] = g_ctab[i];
    for (int i = tid; i < 440; i += 128) soc[i] = (unsigned char)ocl[base*55 + i];

    int j = tid & 15;
    float w[16];
    const float4* W4 = (const float4*)Whh;
    #pragma unroll
    for (int kk = 0; kk < 4; kk++) {
        float4 a = W4[j*4 + kk];
        w[kk*4+0]=a.x; w[kk*4+1]=a.y; w[kk*4+2]=a.z; w[kk*4+3]=a.w;
    }
    float bhv = bhh[j];
    __syncthreads();

    int s = tid >> 4;
    unsigned gmask = 0xFFFFu << (tid & 16);
    const unsigned char* oc = &soc[s * 55];
    int cnt = 0;
    #pragma unroll
    for (int i = 0; i < 4; i++) { int p = j + 16*i; cnt += (p < 55) ? (oc[p] != 18) : 0; }
    #pragma unroll
    for (int o = 8; o; o >>= 1) cnt += __shfl_xor_sync(gmask, cnt, o, 16);
    int len = cnt;

    float h = 0.f;
    for (int t = 0; t < len; t++) {
        int c = oc[t];
        float acc = sct[c*16 + j] + bhv;
        #pragma unroll
        for (int k = 0; k < 16; k++) {
            float hk = __shfl_sync(gmask, h, k, 16);
            acc += w[k]*hk;
        }
        h = ftanh_(acc);
    }
    g_hcls[(base + s)*16 + j] = h;
}

/* ================= K3: pooling + fusion MLP ================= */
__global__ void __launch_bounds__(256) k_fuse(const float* __restrict__ W1, const float* __restrict__ b1,
                                              const float* __restrict__ W2, const float* __restrict__ b2,
                                              float* __restrict__ out)
{
    __shared__ float comb[8][48];
    __shared__ float h1s[8][16];
    int w = threadIdx.x >> 5, lane = threadIdx.x & 31;
    int b = blockIdx.x * 8 + w;
    const float* hf = &g_hbuf[0];
    const float* hb = &g_hbuf[(size_t)NSTR * 16];
    float pooled = 0.f, cnt = 0.f;
    int nb = b * ITEMS;
    for (int i = 0; i < ITEMS; i++) {
        int n = nb + i;
        if (g_len[n]) {
            cnt += 1.f;
            float hv = (lane < 16) ? hf[n*16 + lane] : hb[n*16 + (lane - 16)];
            pooled += hv;
        }
    }
    pooled = pooled / (cnt + 1e-8f);
    if (lane < 16) comb[w][lane] = g_hcls[b*16 + lane];
    comb[w][16 + lane] = pooled;
    __syncwarp();
    if (lane < 16) {
        float a = b1[lane];
        #pragma unroll
        for (int k = 0; k < 48; k++) a += W1[lane*48 + k] * comb[w][k];
        h1s[w][lane] = fmaxf(a, 0.f);
    }
    __syncwarp();
    if (lane < 24) {
        float o = b2[lane];
        #pragma unroll
        for (int k = 0; k < 16; k++) o += W2[lane*16 + k] * h1s[w][k];
        out[b*24 + lane] = o;
    }
}

extern "C" void kernel_launch(void* const* d_in, const int* in_sizes, int n_in,
                              void* d_out, int out_size)
{
    const int*   ocl  = (const int*)d_in[0];
    const int*   strs = (const int*)d_in[1];
    const float* emb  = (const float*)d_in[2];
    const float* rW   = (const float*)d_in[3];
    const float* rWhh = (const float*)d_in[4];
    const float* rbih = (const float*)d_in[5];
    const float* rbhh = (const float*)d_in[6];
    const float* gWf  = (const float*)d_in[7];
    const float* gWhf = (const float*)d_in[8];
    const float* gbif = (const float*)d_in[9];
    const float* gbhf = (const float*)d_in[10];
    const float* gWb  = (const float*)d_in[11];
    const float* gWhb = (const float*)d_in[12];
    const float* gbib = (const float*)d_in[13];
    const float* gbhb = (const float*)d_in[14];
    const float* W1   = (const float*)d_in[15];
    const float* b1   = (const float*)d_in[16];
    const float* W2   = (const float*)d_in[17];
    const float* b2   = (const float*)d_in[18];
    float* out = (float*)d_out;

    k_tables<<<18, 256>>>(emb, gWf, gbif, gbhf, gWb, gbib, gbhb, rW, rbih);
    k_cls<<<128, 128>>>(ocl, rWhh, rbhh);
    dim3 gg(3520, 2);
    k_gru<<<gg, 128>>>(strs, gWhf, gbhf, gWhb, gbhb, emb, ocl,
                       out + OFF_STREMB, out + OFF_CLSEMB);
    k_fuse<<<128, 256>>>(W1, b1, W2, b2, out);
}